// round 1
// baseline (speedup 1.0000x reference)
#include <cuda_runtime.h>
#include <cuda_bf16.h>
#include <math.h>

#define N_TOK 8192
#define DIM   1024
#define NEXP  8
#define DFF   4096
#define NPAIR (2 * N_TOK)

// ---------------- device scratch (no allocations allowed) ----------------
__device__ float g_H[(size_t)NPAIR * DFF];   // 256 MB: silu(x @ w1)
__device__ float g_O[(size_t)NPAIR * DIM];   // 64 MB: weighted expert outputs
__device__ int   g_count[NEXP];
__device__ int   g_offset[NEXP];
__device__ int   g_cursor[NEXP];
__device__ int   g_pair_token[NPAIR];
__device__ float g_pair_weight[NPAIR];
__device__ int   g_tok2pair[2 * N_TOK];
__device__ int   g_tok_e[2 * N_TOK];
__device__ float g_tok_w[2 * N_TOK];

// ---------------- init: zero counters (graph replays!) ----------------
__global__ void k_init() {
    int t = threadIdx.x;
    if (t < NEXP) { g_count[t] = 0; g_cursor[t] = 0; }
}

// ---------------- router: one warp per token ----------------
__global__ void k_router(const float* __restrict__ x,
                         const float* __restrict__ gw) {
    int warp = (blockIdx.x * blockDim.x + threadIdx.x) >> 5;
    int lane = threadIdx.x & 31;
    if (warp >= N_TOK) return;
    const float* xr = x + (size_t)warp * DIM;

    float acc[NEXP];
#pragma unroll
    for (int e = 0; e < NEXP; e++) acc[e] = 0.f;

    for (int d = lane; d < DIM; d += 32) {
        float xv = xr[d];
        const float4* g4 = (const float4*)(gw + (size_t)d * NEXP);
        float4 a = g4[0], b = g4[1];
        acc[0] += xv * a.x; acc[1] += xv * a.y;
        acc[2] += xv * a.z; acc[3] += xv * a.w;
        acc[4] += xv * b.x; acc[5] += xv * b.y;
        acc[6] += xv * b.z; acc[7] += xv * b.w;
    }
#pragma unroll
    for (int e = 0; e < NEXP; e++) {
#pragma unroll
        for (int s = 16; s > 0; s >>= 1)
            acc[e] += __shfl_xor_sync(0xFFFFFFFFu, acc[e], s);
    }
    if (lane == 0) {
        int e0 = 0; float b0 = acc[0];
#pragma unroll
        for (int e = 1; e < NEXP; e++)
            if (acc[e] > b0) { b0 = acc[e]; e0 = e; }
        int e1 = -1; float b1 = -INFINITY;
#pragma unroll
        for (int e = 0; e < NEXP; e++)
            if (e != e0 && acc[e] > b1) { b1 = acc[e]; e1 = e; }
        // renormalized top-2 softmax weights: w0 = 1/(1+exp(l1-l0))
        float w0 = 1.f / (1.f + expf(b1 - b0));
        float w1 = 1.f - w0;
        g_tok_e[2 * warp]     = e0;
        g_tok_e[2 * warp + 1] = e1;
        g_tok_w[2 * warp]     = w0;
        g_tok_w[2 * warp + 1] = w1;
        atomicAdd(&g_count[e0], 1);
        atomicAdd(&g_count[e1], 1);
    }
}

// ---------------- prefix sum over 8 experts ----------------
__global__ void k_prefix() {
    if (threadIdx.x == 0) {
        int s = 0;
        for (int e = 0; e < NEXP; e++) { g_offset[e] = s; s += g_count[e]; }
    }
}

// ---------------- assign compact pair slots ----------------
__global__ void k_assign() {
    int t = blockIdx.x * blockDim.x + threadIdx.x;
    if (t >= N_TOK) return;
#pragma unroll
    for (int s = 0; s < 2; s++) {
        int e = g_tok_e[2 * t + s];
        int pos = g_offset[e] + atomicAdd(&g_cursor[e], 1);
        g_pair_token[pos]  = t;
        g_pair_weight[pos] = g_tok_w[2 * t + s];
        g_tok2pair[2 * t + s] = pos;
    }
}

// ---------------- tiled SGEMM helpers ----------------
#define BM 128
#define BN 128
#define BK 16

// GEMM1: H[p, f] = silu( x[token(p), :] @ w1[e, :, f] )
__global__ __launch_bounds__(256) void k_gemm1(const float* __restrict__ x,
                                               const float* __restrict__ w1) {
    int e = blockIdx.z;
    int cnt = g_count[e];
    int row0 = blockIdx.y * BM;
    if (row0 >= cnt) return;
    int off  = g_offset[e];
    int col0 = blockIdx.x * BN;
    const float* W = w1 + (size_t)e * DIM * DFF;

    __shared__ float As[BK][BM];
    __shared__ float Bs[BK][BN];

    int tid  = threadIdx.x;
    int ty   = tid >> 4;        // 0..15
    int tx   = tid & 15;        // 0..15
    int quad = tid >> 2;        // 0..63
    int l4   = tid & 3;         // 0..3
    int kb   = tid >> 5;        // 0..7
    int fb   = (tid & 31) * 4;  // 0..124

    int rA0 = row0 + quad;
    int rA1 = row0 + quad + 64;
    const float* xr0 = (rA0 < cnt) ? x + (size_t)g_pair_token[off + rA0] * DIM : nullptr;
    const float* xr1 = (rA1 < cnt) ? x + (size_t)g_pair_token[off + rA1] * DIM : nullptr;

    float acc[8][8];
#pragma unroll
    for (int i = 0; i < 8; i++)
#pragma unroll
        for (int j = 0; j < 8; j++) acc[i][j] = 0.f;

    for (int k0 = 0; k0 < DIM; k0 += BK) {
        float4 a0 = xr0 ? *(const float4*)(xr0 + k0 + l4 * 4) : make_float4(0, 0, 0, 0);
        float4 a1 = xr1 ? *(const float4*)(xr1 + k0 + l4 * 4) : make_float4(0, 0, 0, 0);
        float4 b0 = *(const float4*)(W + (size_t)(k0 + kb)     * DFF + col0 + fb);
        float4 b1 = *(const float4*)(W + (size_t)(k0 + kb + 8) * DFF + col0 + fb);
        __syncthreads();
        As[l4 * 4 + 0][quad] = a0.x; As[l4 * 4 + 1][quad] = a0.y;
        As[l4 * 4 + 2][quad] = a0.z; As[l4 * 4 + 3][quad] = a0.w;
        As[l4 * 4 + 0][quad + 64] = a1.x; As[l4 * 4 + 1][quad + 64] = a1.y;
        As[l4 * 4 + 2][quad + 64] = a1.z; As[l4 * 4 + 3][quad + 64] = a1.w;
        *(float4*)&Bs[kb][fb]     = b0;
        *(float4*)&Bs[kb + 8][fb] = b1;
        __syncthreads();
#pragma unroll
        for (int kk = 0; kk < BK; kk++) {
            float a[8], b[8];
#pragma unroll
            for (int i = 0; i < 8; i++) a[i] = As[kk][ty * 8 + i];
#pragma unroll
            for (int j = 0; j < 8; j++) b[j] = Bs[kk][tx * 8 + j];
#pragma unroll
            for (int i = 0; i < 8; i++)
#pragma unroll
                for (int j = 0; j < 8; j++) acc[i][j] += a[i] * b[j];
        }
    }

#pragma unroll
    for (int i = 0; i < 8; i++) {
        int r = row0 + ty * 8 + i;
        if (r < cnt) {
            float* Hrow = g_H + (size_t)(off + r) * DFF + col0 + tx * 8;
#pragma unroll
            for (int j = 0; j < 8; j++) {
                float v = acc[i][j];
                Hrow[j] = v / (1.f + __expf(-v));   // silu
            }
        }
    }
}

// GEMM2: O[p, d] = w_p * ( H[p, :] @ w2[e, :, d] )
__global__ __launch_bounds__(256) void k_gemm2(const float* __restrict__ w2) {
    int e = blockIdx.z;
    int cnt = g_count[e];
    int row0 = blockIdx.y * BM;
    if (row0 >= cnt) return;
    int off  = g_offset[e];
    int col0 = blockIdx.x * BN;
    const float* W = w2 + (size_t)e * DFF * DIM;

    __shared__ float As[BK][BM];
    __shared__ float Bs[BK][BN];

    int tid  = threadIdx.x;
    int ty   = tid >> 4;
    int tx   = tid & 15;
    int quad = tid >> 2;
    int l4   = tid & 3;
    int kb   = tid >> 5;
    int fb   = (tid & 31) * 4;

    int rA0 = row0 + quad;
    int rA1 = row0 + quad + 64;
    const float* hr0 = (rA0 < cnt) ? g_H + (size_t)(off + rA0) * DFF : nullptr;
    const float* hr1 = (rA1 < cnt) ? g_H + (size_t)(off + rA1) * DFF : nullptr;

    float acc[8][8];
#pragma unroll
    for (int i = 0; i < 8; i++)
#pragma unroll
        for (int j = 0; j < 8; j++) acc[i][j] = 0.f;

    for (int k0 = 0; k0 < DFF; k0 += BK) {
        float4 a0 = hr0 ? *(const float4*)(hr0 + k0 + l4 * 4) : make_float4(0, 0, 0, 0);
        float4 a1 = hr1 ? *(const float4*)(hr1 + k0 + l4 * 4) : make_float4(0, 0, 0, 0);
        float4 b0 = *(const float4*)(W + (size_t)(k0 + kb)     * DIM + col0 + fb);
        float4 b1 = *(const float4*)(W + (size_t)(k0 + kb + 8) * DIM + col0 + fb);
        __syncthreads();
        As[l4 * 4 + 0][quad] = a0.x; As[l4 * 4 + 1][quad] = a0.y;
        As[l4 * 4 + 2][quad] = a0.z; As[l4 * 4 + 3][quad] = a0.w;
        As[l4 * 4 + 0][quad + 64] = a1.x; As[l4 * 4 + 1][quad + 64] = a1.y;
        As[l4 * 4 + 2][quad + 64] = a1.z; As[l4 * 4 + 3][quad + 64] = a1.w;
        *(float4*)&Bs[kb][fb]     = b0;
        *(float4*)&Bs[kb + 8][fb] = b1;
        __syncthreads();
#pragma unroll
        for (int kk = 0; kk < BK; kk++) {
            float a[8], b[8];
#pragma unroll
            for (int i = 0; i < 8; i++) a[i] = As[kk][ty * 8 + i];
#pragma unroll
            for (int j = 0; j < 8; j++) b[j] = Bs[kk][tx * 8 + j];
#pragma unroll
            for (int i = 0; i < 8; i++)
#pragma unroll
                for (int j = 0; j < 8; j++) acc[i][j] += a[i] * b[j];
        }
    }

#pragma unroll
    for (int i = 0; i < 8; i++) {
        int r = row0 + ty * 8 + i;
        if (r < cnt) {
            float w = g_pair_weight[off + r];
            float* Orow = g_O + (size_t)(off + r) * DIM + col0 + tx * 8;
#pragma unroll
            for (int j = 0; j < 8; j++) Orow[j] = w * acc[i][j];
        }
    }
}

// ---------------- combine: y[t] = O[pair0(t)] + O[pair1(t)] ----------------
__global__ void k_combine(float* __restrict__ y) {
    int i = blockIdx.x * blockDim.x + threadIdx.x;           // over N*D/4 float4s
    const int V = DIM / 4;
    if (i >= N_TOK * V) return;
    int tok = i / V;
    int c   = i - tok * V;
    int p0 = g_tok2pair[2 * tok];
    int p1 = g_tok2pair[2 * tok + 1];
    float4 a = ((const float4*)(g_O + (size_t)p0 * DIM))[c];
    float4 b = ((const float4*)(g_O + (size_t)p1 * DIM))[c];
    float4 r;
    r.x = a.x + b.x; r.y = a.y + b.y; r.z = a.z + b.z; r.w = a.w + b.w;
    ((float4*)y)[i] = r;
}

// ---------------- launch ----------------
extern "C" void kernel_launch(void* const* d_in, const int* in_sizes, int n_in,
                              void* d_out, int out_size) {
    const float* x  = (const float*)d_in[0];   // [N, D]
    const float* gw = (const float*)d_in[1];   // [D, E]
    const float* w1 = (const float*)d_in[2];   // [E, D, DFF]
    const float* w2 = (const float*)d_in[3];   // [E, DFF, D]
    float* y = (float*)d_out;

    k_init<<<1, 32>>>();
    k_router<<<N_TOK / 8, 256>>>(x, gw);
    k_prefix<<<1, 32>>>();
    k_assign<<<(N_TOK + 255) / 256, 256>>>();

    dim3 g1(DFF / BN, N_TOK / BM, NEXP);   // (32, 64, 8) worst-case, guarded
    k_gemm1<<<g1, 256>>>(x, w1);
    dim3 g2(DIM / BN, N_TOK / BM, NEXP);   // (8, 64, 8)
    k_gemm2<<<g2, 256>>>(w2);

    k_combine<<<(N_TOK * DIM / 4 + 255) / 256, 256>>>(y);
}

// round 3
// speedup vs baseline: 2.0697x; 2.0697x over previous
#include <cuda_runtime.h>
#include <cuda_bf16.h>
#include <math.h>
#include <stdint.h>

#define N_TOK 8192
#define DIM   1024
#define NEXP  8
#define DFF   4096
#define NPAIR (2 * N_TOK)

// ======================= device scratch (statics only) =======================
__device__ __nv_bfloat16 g_X2[2][(size_t)N_TOK * DIM];          // x hi/lo
__device__ __nv_bfloat16 g_W1t[2][(size_t)NEXP * DFF * DIM];    // [e][n][k] hi/lo
__device__ __nv_bfloat16 g_W2t[2][(size_t)NEXP * DIM * DFF];    // [e][d][f] hi/lo
__device__ __nv_bfloat16 g_H2[2][(size_t)NPAIR * DFF];          // silu(h) hi/lo
__device__ float g_O[(size_t)NPAIR * DIM];
__device__ int   g_count[NEXP], g_offset[NEXP], g_cursor[NEXP];
__device__ int   g_pair_token[NPAIR];
__device__ float g_pair_weight[NPAIR];
__device__ int   g_tok2pair[NPAIR];
__device__ int   g_tok_e[NPAIR];
__device__ float g_tok_w[NPAIR];

// ======================= PTX helpers =======================
__device__ __forceinline__ uint32_t smem_u32(const void* p) {
    uint32_t a;
    asm("{ .reg .u64 t; cvta.to.shared.u64 t, %1; cvt.u32.u64 %0, t; }"
        : "=r"(a) : "l"(p));
    return a;
}
__device__ __forceinline__ void cp16(uint32_t dst, const void* src, bool valid) {
    int sz = valid ? 16 : 0;
    asm volatile("cp.async.cg.shared.global [%0], [%1], 16, %2;"
                 :: "r"(dst), "l"(src), "r"(sz));
}
#define CP_COMMIT() asm volatile("cp.async.commit_group;" ::: "memory")
#define CP_WAIT(n)  asm volatile("cp.async.wait_group %0;" :: "n"(n) : "memory")

__device__ __forceinline__ void ldsm_x4(uint32_t* r, uint32_t addr) {
    asm volatile("ldmatrix.sync.aligned.m8n8.x4.shared.b16 {%0,%1,%2,%3}, [%4];"
                 : "=r"(r[0]), "=r"(r[1]), "=r"(r[2]), "=r"(r[3]) : "r"(addr));
}
__device__ __forceinline__ void mma_bf16(float* c, const uint32_t* a,
                                         uint32_t b0, uint32_t b1) {
    asm volatile("mma.sync.aligned.m16n8k16.row.col.f32.bf16.bf16.f32 "
                 "{%0,%1,%2,%3},{%4,%5,%6,%7},{%8,%9},{%0,%1,%2,%3};"
                 : "+f"(c[0]), "+f"(c[1]), "+f"(c[2]), "+f"(c[3])
                 : "r"(a[0]), "r"(a[1]), "r"(a[2]), "r"(a[3]), "r"(b0), "r"(b1));
}

// ======================= routing kernels =======================
__global__ void k_init() {
    int t = threadIdx.x;
    if (t < NEXP) { g_count[t] = 0; g_cursor[t] = 0; }
}

__global__ void k_router(const float* __restrict__ x, const float* __restrict__ gw) {
    int warp = (blockIdx.x * blockDim.x + threadIdx.x) >> 5;
    int lane = threadIdx.x & 31;
    if (warp >= N_TOK) return;
    const float* xr = x + (size_t)warp * DIM;
    float acc[NEXP];
#pragma unroll
    for (int e = 0; e < NEXP; e++) acc[e] = 0.f;
    for (int d = lane; d < DIM; d += 32) {
        float xv = xr[d];
        const float4* g4 = (const float4*)(gw + (size_t)d * NEXP);
        float4 a = g4[0], b = g4[1];
        acc[0] += xv * a.x; acc[1] += xv * a.y; acc[2] += xv * a.z; acc[3] += xv * a.w;
        acc[4] += xv * b.x; acc[5] += xv * b.y; acc[6] += xv * b.z; acc[7] += xv * b.w;
    }
#pragma unroll
    for (int e = 0; e < NEXP; e++)
#pragma unroll
        for (int s = 16; s > 0; s >>= 1)
            acc[e] += __shfl_xor_sync(0xFFFFFFFFu, acc[e], s);
    if (lane == 0) {
        int e0 = 0; float b0 = acc[0];
#pragma unroll
        for (int e = 1; e < NEXP; e++) if (acc[e] > b0) { b0 = acc[e]; e0 = e; }
        int e1 = -1; float b1 = -INFINITY;
#pragma unroll
        for (int e = 0; e < NEXP; e++) if (e != e0 && acc[e] > b1) { b1 = acc[e]; e1 = e; }
        float w0 = 1.f / (1.f + expf(b1 - b0));
        g_tok_e[2 * warp] = e0;      g_tok_e[2 * warp + 1] = e1;
        g_tok_w[2 * warp] = w0;      g_tok_w[2 * warp + 1] = 1.f - w0;
        atomicAdd(&g_count[e0], 1);
        atomicAdd(&g_count[e1], 1);
    }
}

__global__ void k_prefix() {
    if (threadIdx.x == 0) {
        int s = 0;
        for (int e = 0; e < NEXP; e++) { g_offset[e] = s; s += g_count[e]; }
    }
}

__global__ void k_assign() {
    int t = blockIdx.x * blockDim.x + threadIdx.x;
    if (t >= N_TOK) return;
#pragma unroll
    for (int s = 0; s < 2; s++) {
        int e = g_tok_e[2 * t + s];
        int pos = g_offset[e] + atomicAdd(&g_cursor[e], 1);
        g_pair_token[pos]  = t;
        g_pair_weight[pos] = g_tok_w[2 * t + s];
        g_tok2pair[2 * t + s] = pos;
    }
}

// ======================= converts =======================
__device__ __forceinline__ void split_bf16(float v, __nv_bfloat16& hi, __nv_bfloat16& lo) {
    hi = __float2bfloat16(v);
    lo = __float2bfloat16(v - __bfloat162float(hi));
}

__global__ void k_convert_x(const float* __restrict__ x) {
    size_t i = (size_t)blockIdx.x * blockDim.x + threadIdx.x;   // over float4s
    if (i >= (size_t)N_TOK * DIM / 4) return;
    float4 v = ((const float4*)x)[i];
    __nv_bfloat16 h0, l0, h1, l1, h2, l2, h3, l3;
    split_bf16(v.x, h0, l0); split_bf16(v.y, h1, l1);
    split_bf16(v.z, h2, l2); split_bf16(v.w, h3, l3);
    __nv_bfloat162 a; a.x = h0; a.y = h1;
    __nv_bfloat162 b; b.x = h2; b.y = h3;
    __nv_bfloat162 c; c.x = l0; c.y = l1;
    __nv_bfloat162 d; d.x = l2; d.y = l3;
    ((__nv_bfloat162*)&g_X2[0][i * 4])[0] = a;
    ((__nv_bfloat162*)&g_X2[0][i * 4])[1] = b;
    ((__nv_bfloat162*)&g_X2[1][i * 4])[0] = c;
    ((__nv_bfloat162*)&g_X2[1][i * 4])[1] = d;
}

// W: [e][K][Ncols] fp32  ->  Th/Tl: [e][Ncols][K] bf16 (transposed, hi/lo)
__global__ void k_convert_w(const float* __restrict__ W,
                            __nv_bfloat16* __restrict__ Th,
                            __nv_bfloat16* __restrict__ Tl,
                            int K, int Ncols) {
    __shared__ float tile[32][33];
    int e = blockIdx.z;
    int n0 = blockIdx.x * 32, k0 = blockIdx.y * 32;
    int tx = threadIdx.x, ty = threadIdx.y;
    const float* We = W + (size_t)e * K * Ncols;
#pragma unroll
    for (int j = 0; j < 4; j++)
        tile[ty + 8 * j][tx] = We[(size_t)(k0 + ty + 8 * j) * Ncols + n0 + tx];
    __syncthreads();
    size_t obase = (size_t)e * Ncols * K;
#pragma unroll
    for (int j = 0; j < 4; j++) {
        float v = tile[tx][ty + 8 * j];
        __nv_bfloat16 hi, lo; split_bf16(v, hi, lo);
        size_t o = obase + (size_t)(n0 + ty + 8 * j) * K + k0 + tx;
        Th[o] = hi; Tl[o] = lo;
    }
}

// ======================= mma.sync GEMM =======================
// Smem stage layout: 4 planes (Ah, Al, Bh, Bl), each 128 rows x 32 bf16,
// row stride padded to 40 bf16 (80B) for conflict-free ldmatrix.
#define ROW_B   80                      // bytes per padded row
#define PLANE_B (128 * ROW_B)           // 10240
#define STAGE_B (4 * PLANE_B)           // 40960
#define NSTAGE  3
#define SMEM_BYTES (NSTAGE * STAGE_B)   // 122880

// G1: H2 = silu(X2_gathered @ W1t^T)   K=1024 (NC=32)
// !G1: O = w * (H2 @ W2t^T)            K=4096 (NC=128)
template <int NC, bool G1>
__global__ __launch_bounds__(256) void k_mma() {
    const int e    = blockIdx.z;
    const int cnt  = g_count[e];
    const int row0 = blockIdx.y * 128;
    if (row0 >= cnt) return;
    const int off  = g_offset[e];
    const int n0   = blockIdx.x * 128;

    extern __shared__ char dynsmem[];
    const uint32_t sb = smem_u32(dynsmem);

    const int tid  = threadIdx.x;
    const int lane = tid & 31;
    const int wid  = tid >> 5;
    const int wm   = wid & 1;      // 0..1 (64 rows each)
    const int wn   = wid >> 1;     // 0..3 (32 cols each)

    // ---- global load setup: thread loads row r = tid>>1, half = tid&1 (32B) ----
    const int r    = tid >> 1;
    const int half = tid & 1;
    const int row  = row0 + r;
    const bool vA  = row < cnt;

    const char* srcAh;
    const char* srcAl;
    const char* srcBh;
    const char* srcBl;
    if (G1) {
        int tok = vA ? g_pair_token[off + row] : 0;
        srcAh = (const char*)(&g_X2[0][0] + (size_t)tok * DIM) + half * 32;
        srcAl = (const char*)(&g_X2[1][0] + (size_t)tok * DIM) + half * 32;
        srcBh = (const char*)(&g_W1t[0][0] + ((size_t)e * DFF + n0 + r) * DIM) + half * 32;
        srcBl = (const char*)(&g_W1t[1][0] + ((size_t)e * DFF + n0 + r) * DIM) + half * 32;
    } else {
        size_t p = (size_t)(vA ? off + row : 0);
        srcAh = (const char*)(&g_H2[0][0] + p * DFF) + half * 32;
        srcAl = (const char*)(&g_H2[1][0] + p * DFF) + half * 32;
        srcBh = (const char*)(&g_W2t[0][0] + ((size_t)e * DIM + n0 + r) * DFF) + half * 32;
        srcBl = (const char*)(&g_W2t[1][0] + ((size_t)e * DIM + n0 + r) * DFF) + half * 32;
    }
    const uint32_t dstOff = (uint32_t)(r * ROW_B + half * 32);

    // ---- ldmatrix per-thread addresses (within a plane) ----
    const int mat  = lane >> 3;
    const int lrow = lane & 7;
    // A: row = wm*64 + tm*16 + (mat&1)*8 + lrow ; col bytes = (mat>>1)*16 + ks*32
    const uint32_t aOff = (uint32_t)((wm * 64 + (mat & 1) * 8 + lrow) * ROW_B + (mat >> 1) * 16);
    // B: row = wn*32 + tp*16 + (mat>>1)*8 + lrow ; col bytes = (mat&1)*16 + ks*32
    const uint32_t bOff = (uint32_t)((wn * 32 + (mat >> 1) * 8 + lrow) * ROW_B + (mat & 1) * 16);

    float c[4][4][4];
#pragma unroll
    for (int i = 0; i < 4; i++)
#pragma unroll
        for (int j = 0; j < 4; j++)
#pragma unroll
            for (int q = 0; q < 4; q++) c[i][j][q] = 0.f;

    // ---- pipelined main loop ----
    auto load_stage = [&](int cidx) {
        uint32_t st = sb + (uint32_t)(cidx % NSTAGE) * STAGE_B;
        size_t ko = (size_t)cidx * 64;   // 32 bf16 = 64 bytes per chunk
        cp16(st + 0 * PLANE_B + dstOff,      srcAh + ko, vA);
        cp16(st + 0 * PLANE_B + dstOff + 16, srcAh + ko + 16, vA);
        cp16(st + 1 * PLANE_B + dstOff,      srcAl + ko, vA);
        cp16(st + 1 * PLANE_B + dstOff + 16, srcAl + ko + 16, vA);
        cp16(st + 2 * PLANE_B + dstOff,      srcBh + ko, true);
        cp16(st + 2 * PLANE_B + dstOff + 16, srcBh + ko + 16, true);
        cp16(st + 3 * PLANE_B + dstOff,      srcBl + ko, true);
        cp16(st + 3 * PLANE_B + dstOff + 16, srcBl + ko + 16, true);
        CP_COMMIT();
    };

    load_stage(0);
    load_stage(1);

    for (int cidx = 0; cidx < NC; cidx++) {
        CP_WAIT(1);
        __syncthreads();
        if (cidx + 2 < NC) load_stage(cidx + 2);

        uint32_t st = sb + (uint32_t)(cidx % NSTAGE) * STAGE_B;
#pragma unroll
        for (int ks = 0; ks < 2; ks++) {
            uint32_t kso = (uint32_t)(ks * 32);
            uint32_t a[4][4], bh[2][4], bl[2][4];
#pragma unroll
            for (int tm = 0; tm < 4; tm++)
                ldsm_x4(a[tm], st + 0 * PLANE_B + aOff + (uint32_t)(tm * 16 * ROW_B) + kso);
#pragma unroll
            for (int tp = 0; tp < 2; tp++)
                ldsm_x4(bh[tp], st + 2 * PLANE_B + bOff + (uint32_t)(tp * 16 * ROW_B) + kso);
            // pass 1: Ah * Bh
#pragma unroll
            for (int tm = 0; tm < 4; tm++)
#pragma unroll
                for (int tp = 0; tp < 2; tp++) {
                    mma_bf16(c[tm][tp * 2 + 0], a[tm], bh[tp][0], bh[tp][1]);
                    mma_bf16(c[tm][tp * 2 + 1], a[tm], bh[tp][2], bh[tp][3]);
                }
            // pass 2: Ah * Bl
#pragma unroll
            for (int tp = 0; tp < 2; tp++)
                ldsm_x4(bl[tp], st + 3 * PLANE_B + bOff + (uint32_t)(tp * 16 * ROW_B) + kso);
#pragma unroll
            for (int tm = 0; tm < 4; tm++)
#pragma unroll
                for (int tp = 0; tp < 2; tp++) {
                    mma_bf16(c[tm][tp * 2 + 0], a[tm], bl[tp][0], bl[tp][1]);
                    mma_bf16(c[tm][tp * 2 + 1], a[tm], bl[tp][2], bl[tp][3]);
                }
            // pass 3: Al * Bh
#pragma unroll
            for (int tm = 0; tm < 4; tm++)
                ldsm_x4(a[tm], st + 1 * PLANE_B + aOff + (uint32_t)(tm * 16 * ROW_B) + kso);
#pragma unroll
            for (int tm = 0; tm < 4; tm++)
#pragma unroll
                for (int tp = 0; tp < 2; tp++) {
                    mma_bf16(c[tm][tp * 2 + 0], a[tm], bh[tp][0], bh[tp][1]);
                    mma_bf16(c[tm][tp * 2 + 1], a[tm], bh[tp][2], bh[tp][3]);
                }
        }
    }

    // ---- epilogue ----
    const int g   = lane >> 2;
    const int tig = lane & 3;
#pragma unroll
    for (int tm = 0; tm < 4; tm++) {
#pragma unroll
        for (int half_m = 0; half_m < 2; half_m++) {
            int rr = row0 + wm * 64 + tm * 16 + g + half_m * 8;
            if (rr >= cnt) continue;
            if (G1) {
                size_t hrow = (size_t)(off + rr) * DFF + n0 + wn * 32 + tig * 2;
#pragma unroll
                for (int tn = 0; tn < 4; tn++) {
                    float v0 = c[tm][tn][half_m * 2 + 0];
                    float v1 = c[tm][tn][half_m * 2 + 1];
                    v0 = v0 / (1.f + __expf(-v0));
                    v1 = v1 / (1.f + __expf(-v1));
                    __nv_bfloat16 h0, l0, h1, l1;
                    split_bf16(v0, h0, l0);
                    split_bf16(v1, h1, l1);
                    __nv_bfloat162 hh; hh.x = h0; hh.y = h1;
                    __nv_bfloat162 ll; ll.x = l0; ll.y = l1;
                    *(__nv_bfloat162*)(&g_H2[0][0] + hrow + tn * 8) = hh;
                    *(__nv_bfloat162*)(&g_H2[1][0] + hrow + tn * 8) = ll;
                }
            } else {
                float wgt = g_pair_weight[off + rr];
                size_t orow = (size_t)(off + rr) * DIM + n0 + wn * 32 + tig * 2;
#pragma unroll
                for (int tn = 0; tn < 4; tn++) {
                    float2 o;
                    o.x = wgt * c[tm][tn][half_m * 2 + 0];
                    o.y = wgt * c[tm][tn][half_m * 2 + 1];
                    *(float2*)(g_O + orow + tn * 8) = o;
                }
            }
        }
    }
}

// ======================= combine =======================
__global__ void k_combine(float* __restrict__ y) {
    int i = blockIdx.x * blockDim.x + threadIdx.x;
    const int V = DIM / 4;
    if (i >= N_TOK * V) return;
    int tok = i / V;
    int c   = i - tok * V;
    int p0 = g_tok2pair[2 * tok];
    int p1 = g_tok2pair[2 * tok + 1];
    float4 a = ((const float4*)(g_O + (size_t)p0 * DIM))[c];
    float4 b = ((const float4*)(g_O + (size_t)p1 * DIM))[c];
    float4 r;
    r.x = a.x + b.x; r.y = a.y + b.y; r.z = a.z + b.z; r.w = a.w + b.w;
    ((float4*)y)[i] = r;
}

// ======================= launch =======================
extern "C" void kernel_launch(void* const* d_in, const int* in_sizes, int n_in,
                              void* d_out, int out_size) {
    const float* x  = (const float*)d_in[0];   // [N, D]
    const float* gw = (const float*)d_in[1];   // [D, E]
    const float* w1 = (const float*)d_in[2];   // [E, D, DFF]
    const float* w2 = (const float*)d_in[3];   // [E, DFF, D]
    float* y = (float*)d_out;

    cudaFuncSetAttribute((const void*)k_mma<DIM / 32, true>,
                         cudaFuncAttributeMaxDynamicSharedMemorySize, SMEM_BYTES);
    cudaFuncSetAttribute((const void*)k_mma<DFF / 32, false>,
                         cudaFuncAttributeMaxDynamicSharedMemorySize, SMEM_BYTES);

    k_init<<<1, 32>>>();
    k_convert_x<<<(N_TOK * DIM / 4 + 255) / 256, 256>>>(x);

    __nv_bfloat16* w1h; __nv_bfloat16* w2h;
    cudaGetSymbolAddress((void**)&w1h, g_W1t);
    cudaGetSymbolAddress((void**)&w2h, g_W2t);
    __nv_bfloat16* w1l = w1h + (size_t)NEXP * DFF * DIM;
    __nv_bfloat16* w2l = w2h + (size_t)NEXP * DIM * DFF;

    // W1: [e][K=1024][N=4096] -> [e][n][k]
    k_convert_w<<<dim3(DFF / 32, DIM / 32, NEXP), dim3(32, 8)>>>(w1, w1h, w1l, DIM, DFF);
    // W2: [e][K=4096][N=1024] -> [e][d][f]
    k_convert_w<<<dim3(DIM / 32, DFF / 32, NEXP), dim3(32, 8)>>>(w2, w2h, w2l, DFF, DIM);

    k_router<<<N_TOK / 8, 256>>>(x, gw);
    k_prefix<<<1, 32>>>();
    k_assign<<<(N_TOK + 255) / 256, 256>>>();

    k_mma<DIM / 32, true><<<dim3(DFF / 128, NPAIR / 128, NEXP), 256, SMEM_BYTES>>>();
    k_mma<DFF / 32, false><<<dim3(DIM / 128, NPAIR / 128, NEXP), 256, SMEM_BYTES>>>();

    k_combine<<<(N_TOK * DIM / 4 + 255) / 256, 256>>>(y);
}

// round 4
// speedup vs baseline: 2.4857x; 1.2010x over previous
#include <cuda_runtime.h>
#include <cuda_bf16.h>
#include <math.h>
#include <stdint.h>

#define N_TOK 8192
#define DIM   1024
#define NEXP  8
#define DFF   4096
#define NPAIR (2 * N_TOK)

// ======================= device scratch (statics only) =======================
__device__ __nv_bfloat16 g_X2[2][(size_t)N_TOK * DIM];          // x hi/lo
__device__ __nv_bfloat16 g_W1t[2][(size_t)NEXP * DFF * DIM];    // [e][n][k] hi/lo
__device__ __nv_bfloat16 g_W2t[2][(size_t)NEXP * DIM * DFF];    // [e][d][f] hi/lo
__device__ __nv_bfloat16 g_H2[2][(size_t)NPAIR * DFF];          // silu(h) hi/lo
__device__ float g_O[(size_t)NPAIR * DIM];
__device__ int   g_count[NEXP], g_offset[NEXP], g_cursor[NEXP];
__device__ int   g_pair_token[NPAIR];
__device__ float g_pair_weight[NPAIR];
__device__ int   g_tok2pair[NPAIR];
__device__ int   g_tok_e[NPAIR];
__device__ float g_tok_w[NPAIR];

// ======================= PTX helpers =======================
__device__ __forceinline__ uint32_t smem_u32(const void* p) {
    uint32_t a;
    asm("{ .reg .u64 t; cvta.to.shared.u64 t, %1; cvt.u32.u64 %0, t; }"
        : "=r"(a) : "l"(p));
    return a;
}
__device__ __forceinline__ void cp16(uint32_t dst, const void* src, bool valid) {
    int sz = valid ? 16 : 0;
    asm volatile("cp.async.cg.shared.global [%0], [%1], 16, %2;"
                 :: "r"(dst), "l"(src), "r"(sz));
}
#define CP_COMMIT() asm volatile("cp.async.commit_group;" ::: "memory")
#define CP_WAIT(n)  asm volatile("cp.async.wait_group %0;" :: "n"(n) : "memory")

__device__ __forceinline__ void ldsm_x4(uint32_t* r, uint32_t addr) {
    asm volatile("ldmatrix.sync.aligned.m8n8.x4.shared.b16 {%0,%1,%2,%3}, [%4];"
                 : "=r"(r[0]), "=r"(r[1]), "=r"(r[2]), "=r"(r[3]) : "r"(addr));
}
__device__ __forceinline__ void mma_bf16(float* c, const uint32_t* a,
                                         uint32_t b0, uint32_t b1) {
    asm volatile("mma.sync.aligned.m16n8k16.row.col.f32.bf16.bf16.f32 "
                 "{%0,%1,%2,%3},{%4,%5,%6,%7},{%8,%9},{%0,%1,%2,%3};"
                 : "+f"(c[0]), "+f"(c[1]), "+f"(c[2]), "+f"(c[3])
                 : "r"(a[0]), "r"(a[1]), "r"(a[2]), "r"(a[3]), "r"(b0), "r"(b1));
}

// ======================= routing kernels =======================
__global__ void k_init() {
    int t = threadIdx.x;
    if (t < NEXP) { g_count[t] = 0; g_cursor[t] = 0; }
}

__global__ void k_router(const float* __restrict__ x, const float* __restrict__ gw) {
    int warp = (blockIdx.x * blockDim.x + threadIdx.x) >> 5;
    int lane = threadIdx.x & 31;
    if (warp >= N_TOK) return;
    const float* xr = x + (size_t)warp * DIM;
    float acc[NEXP];
#pragma unroll
    for (int e = 0; e < NEXP; e++) acc[e] = 0.f;
    for (int d = lane; d < DIM; d += 32) {
        float xv = xr[d];
        const float4* g4 = (const float4*)(gw + (size_t)d * NEXP);
        float4 a = g4[0], b = g4[1];
        acc[0] += xv * a.x; acc[1] += xv * a.y; acc[2] += xv * a.z; acc[3] += xv * a.w;
        acc[4] += xv * b.x; acc[5] += xv * b.y; acc[6] += xv * b.z; acc[7] += xv * b.w;
    }
#pragma unroll
    for (int e = 0; e < NEXP; e++)
#pragma unroll
        for (int s = 16; s > 0; s >>= 1)
            acc[e] += __shfl_xor_sync(0xFFFFFFFFu, acc[e], s);
    if (lane == 0) {
        int e0 = 0; float b0 = acc[0];
#pragma unroll
        for (int e = 1; e < NEXP; e++) if (acc[e] > b0) { b0 = acc[e]; e0 = e; }
        int e1 = -1; float b1 = -INFINITY;
#pragma unroll
        for (int e = 0; e < NEXP; e++) if (e != e0 && acc[e] > b1) { b1 = acc[e]; e1 = e; }
        float w0 = 1.f / (1.f + expf(b1 - b0));
        g_tok_e[2 * warp] = e0;      g_tok_e[2 * warp + 1] = e1;
        g_tok_w[2 * warp] = w0;      g_tok_w[2 * warp + 1] = 1.f - w0;
        atomicAdd(&g_count[e0], 1);
        atomicAdd(&g_count[e1], 1);
    }
}

__global__ void k_prefix() {
    if (threadIdx.x == 0) {
        int s = 0;
        for (int e = 0; e < NEXP; e++) { g_offset[e] = s; s += g_count[e]; }
    }
}

__global__ void k_assign() {
    int t = blockIdx.x * blockDim.x + threadIdx.x;
    if (t >= N_TOK) return;
#pragma unroll
    for (int s = 0; s < 2; s++) {
        int e = g_tok_e[2 * t + s];
        int pos = g_offset[e] + atomicAdd(&g_cursor[e], 1);
        g_pair_token[pos]  = t;
        g_pair_weight[pos] = g_tok_w[2 * t + s];
        g_tok2pair[2 * t + s] = pos;
    }
}

// ======================= converts =======================
__device__ __forceinline__ void split_bf16(float v, __nv_bfloat16& hi, __nv_bfloat16& lo) {
    hi = __float2bfloat16(v);
    lo = __float2bfloat16(v - __bfloat162float(hi));
}

__global__ void k_convert_x(const float* __restrict__ x) {
    size_t i = (size_t)blockIdx.x * blockDim.x + threadIdx.x;   // over float4s
    if (i >= (size_t)N_TOK * DIM / 4) return;
    float4 v = ((const float4*)x)[i];
    __nv_bfloat16 h0, l0, h1, l1, h2, l2, h3, l3;
    split_bf16(v.x, h0, l0); split_bf16(v.y, h1, l1);
    split_bf16(v.z, h2, l2); split_bf16(v.w, h3, l3);
    __nv_bfloat162 a; a.x = h0; a.y = h1;
    __nv_bfloat162 b; b.x = h2; b.y = h3;
    __nv_bfloat162 c; c.x = l0; c.y = l1;
    __nv_bfloat162 d; d.x = l2; d.y = l3;
    ((__nv_bfloat162*)&g_X2[0][i * 4])[0] = a;
    ((__nv_bfloat162*)&g_X2[0][i * 4])[1] = b;
    ((__nv_bfloat162*)&g_X2[1][i * 4])[0] = c;
    ((__nv_bfloat162*)&g_X2[1][i * 4])[1] = d;
}

// W: [e][K][Ncols] fp32  ->  Th/Tl: [e][Ncols][K] bf16 (transposed, hi/lo)
__global__ void k_convert_w(const float* __restrict__ W,
                            __nv_bfloat16* __restrict__ Th,
                            __nv_bfloat16* __restrict__ Tl,
                            int K, int Ncols) {
    __shared__ float tile[32][33];
    int e = blockIdx.z;
    int n0 = blockIdx.x * 32, k0 = blockIdx.y * 32;
    int tx = threadIdx.x, ty = threadIdx.y;
    const float* We = W + (size_t)e * K * Ncols;
#pragma unroll
    for (int j = 0; j < 4; j++)
        tile[ty + 8 * j][tx] = We[(size_t)(k0 + ty + 8 * j) * Ncols + n0 + tx];
    __syncthreads();
    size_t obase = (size_t)e * Ncols * K;
#pragma unroll
    for (int j = 0; j < 4; j++) {
        float v = tile[tx][ty + 8 * j];
        __nv_bfloat16 hi, lo; split_bf16(v, hi, lo);
        size_t o = obase + (size_t)(n0 + ty + 8 * j) * K + k0 + tx;
        Th[o] = hi; Tl[o] = lo;
    }
}

// ======================= mma.sync GEMM =======================
// Smem stage layout: 4 planes (Ah, Al, Bh, Bl), each 128 rows x 32 bf16,
// row stride padded to 40 bf16 (80B) for conflict-free ldmatrix.
#define ROW_B   80                      // bytes per padded row
#define PLANE_B (128 * ROW_B)           // 10240
#define STAGE_B (4 * PLANE_B)           // 40960
#define NSTAGE  2
#define SMEM_BYTES (NSTAGE * STAGE_B)   // 81920 -> 2 CTAs/SM

// G1: H2 = silu(X2_gathered @ W1t^T)   K=1024 (NC=32)
// !G1: O = w * (H2 @ W2t^T)            K=4096 (NC=128)
template <int NC, bool G1>
__global__ __launch_bounds__(256, 2) void k_mma() {
    const int e    = blockIdx.z;
    const int cnt  = g_count[e];
    const int row0 = blockIdx.y * 128;
    if (row0 >= cnt) return;
    const int off  = g_offset[e];
    const int n0   = blockIdx.x * 128;

    extern __shared__ char dynsmem[];
    const uint32_t sb = smem_u32(dynsmem);

    const int tid  = threadIdx.x;
    const int lane = tid & 31;
    const int wid  = tid >> 5;
    const int wm   = wid & 1;      // 0..1 (64 rows each)
    const int wn   = wid >> 1;     // 0..3 (32 cols each)

    // ---- global load setup: thread loads row r = tid>>1, half = tid&1 (32B) ----
    const int r    = tid >> 1;
    const int half = tid & 1;
    const int row  = row0 + r;
    const bool vA  = row < cnt;

    const char* srcAh;
    const char* srcAl;
    const char* srcBh;
    const char* srcBl;
    if (G1) {
        int tok = vA ? g_pair_token[off + row] : 0;
        srcAh = (const char*)(&g_X2[0][0] + (size_t)tok * DIM) + half * 32;
        srcAl = (const char*)(&g_X2[1][0] + (size_t)tok * DIM) + half * 32;
        srcBh = (const char*)(&g_W1t[0][0] + ((size_t)e * DFF + n0 + r) * DIM) + half * 32;
        srcBl = (const char*)(&g_W1t[1][0] + ((size_t)e * DFF + n0 + r) * DIM) + half * 32;
    } else {
        size_t p = (size_t)(vA ? off + row : 0);
        srcAh = (const char*)(&g_H2[0][0] + p * DFF) + half * 32;
        srcAl = (const char*)(&g_H2[1][0] + p * DFF) + half * 32;
        srcBh = (const char*)(&g_W2t[0][0] + ((size_t)e * DIM + n0 + r) * DFF) + half * 32;
        srcBl = (const char*)(&g_W2t[1][0] + ((size_t)e * DIM + n0 + r) * DFF) + half * 32;
    }
    const uint32_t dstOff = (uint32_t)(r * ROW_B + half * 32);

    // ---- ldmatrix per-thread addresses (within a plane) ----
    const int mat  = lane >> 3;
    const int lrow = lane & 7;
    // A: row = wm*64 + tm*16 + (mat&1)*8 + lrow ; col bytes = (mat>>1)*16 + ks*32
    const uint32_t aOff = (uint32_t)((wm * 64 + (mat & 1) * 8 + lrow) * ROW_B + (mat >> 1) * 16);
    // B: row = wn*32 + tp*16 + (mat>>1)*8 + lrow ; col bytes = (mat&1)*16 + ks*32
    const uint32_t bOff = (uint32_t)((wn * 32 + (mat >> 1) * 8 + lrow) * ROW_B + (mat & 1) * 16);

    float c[4][4][4];
#pragma unroll
    for (int i = 0; i < 4; i++)
#pragma unroll
        for (int j = 0; j < 4; j++)
#pragma unroll
            for (int q = 0; q < 4; q++) c[i][j][q] = 0.f;

    auto load_stage = [&](int cidx) {
        uint32_t st = sb + (uint32_t)(cidx & 1) * STAGE_B;
        size_t ko = (size_t)cidx * 64;   // 32 bf16 = 64 bytes per chunk
        cp16(st + 0 * PLANE_B + dstOff,      srcAh + ko, vA);
        cp16(st + 0 * PLANE_B + dstOff + 16, srcAh + ko + 16, vA);
        cp16(st + 1 * PLANE_B + dstOff,      srcAl + ko, vA);
        cp16(st + 1 * PLANE_B + dstOff + 16, srcAl + ko + 16, vA);
        cp16(st + 2 * PLANE_B + dstOff,      srcBh + ko, true);
        cp16(st + 2 * PLANE_B + dstOff + 16, srcBh + ko + 16, true);
        cp16(st + 3 * PLANE_B + dstOff,      srcBl + ko, true);
        cp16(st + 3 * PLANE_B + dstOff + 16, srcBl + ko + 16, true);
        CP_COMMIT();
    };

    load_stage(0);

    for (int cidx = 0; cidx < NC; cidx++) {
        CP_WAIT(0);                 // stage cidx data landed (this thread)
        __syncthreads();            // visible to all; prev compute done everywhere
        if (cidx + 1 < NC) load_stage(cidx + 1);   // fills the other buffer

        uint32_t st = sb + (uint32_t)(cidx & 1) * STAGE_B;
#pragma unroll
        for (int ks = 0; ks < 2; ks++) {
            uint32_t kso = (uint32_t)(ks * 32);
            uint32_t a[4][4], bh[2][4], bl[2][4];
#pragma unroll
            for (int tm = 0; tm < 4; tm++)
                ldsm_x4(a[tm], st + 0 * PLANE_B + aOff + (uint32_t)(tm * 16 * ROW_B) + kso);
#pragma unroll
            for (int tp = 0; tp < 2; tp++)
                ldsm_x4(bh[tp], st + 2 * PLANE_B + bOff + (uint32_t)(tp * 16 * ROW_B) + kso);
            // pass 1: Ah * Bh
#pragma unroll
            for (int tm = 0; tm < 4; tm++)
#pragma unroll
                for (int tp = 0; tp < 2; tp++) {
                    mma_bf16(c[tm][tp * 2 + 0], a[tm], bh[tp][0], bh[tp][1]);
                    mma_bf16(c[tm][tp * 2 + 1], a[tm], bh[tp][2], bh[tp][3]);
                }
            // pass 2: Ah * Bl
#pragma unroll
            for (int tp = 0; tp < 2; tp++)
                ldsm_x4(bl[tp], st + 3 * PLANE_B + bOff + (uint32_t)(tp * 16 * ROW_B) + kso);
#pragma unroll
            for (int tm = 0; tm < 4; tm++)
#pragma unroll
                for (int tp = 0; tp < 2; tp++) {
                    mma_bf16(c[tm][tp * 2 + 0], a[tm], bl[tp][0], bl[tp][1]);
                    mma_bf16(c[tm][tp * 2 + 1], a[tm], bl[tp][2], bl[tp][3]);
                }
            // pass 3: Al * Bh
#pragma unroll
            for (int tm = 0; tm < 4; tm++)
                ldsm_x4(a[tm], st + 1 * PLANE_B + aOff + (uint32_t)(tm * 16 * ROW_B) + kso);
#pragma unroll
            for (int tm = 0; tm < 4; tm++)
#pragma unroll
                for (int tp = 0; tp < 2; tp++) {
                    mma_bf16(c[tm][tp * 2 + 0], a[tm], bh[tp][0], bh[tp][1]);
                    mma_bf16(c[tm][tp * 2 + 1], a[tm], bh[tp][2], bh[tp][3]);
                }
        }
    }

    // ---- epilogue ----
    const int g   = lane >> 2;
    const int tig = lane & 3;
#pragma unroll
    for (int tm = 0; tm < 4; tm++) {
#pragma unroll
        for (int half_m = 0; half_m < 2; half_m++) {
            int rr = row0 + wm * 64 + tm * 16 + g + half_m * 8;
            if (rr >= cnt) continue;
            if (G1) {
                size_t hrow = (size_t)(off + rr) * DFF + n0 + wn * 32 + tig * 2;
#pragma unroll
                for (int tn = 0; tn < 4; tn++) {
                    float v0 = c[tm][tn][half_m * 2 + 0];
                    float v1 = c[tm][tn][half_m * 2 + 1];
                    v0 = v0 / (1.f + __expf(-v0));
                    v1 = v1 / (1.f + __expf(-v1));
                    __nv_bfloat16 h0, l0, h1, l1;
                    split_bf16(v0, h0, l0);
                    split_bf16(v1, h1, l1);
                    __nv_bfloat162 hh; hh.x = h0; hh.y = h1;
                    __nv_bfloat162 ll; ll.x = l0; ll.y = l1;
                    *(__nv_bfloat162*)(&g_H2[0][0] + hrow + tn * 8) = hh;
                    *(__nv_bfloat162*)(&g_H2[1][0] + hrow + tn * 8) = ll;
                }
            } else {
                float wgt = g_pair_weight[off + rr];
                size_t orow = (size_t)(off + rr) * DIM + n0 + wn * 32 + tig * 2;
#pragma unroll
                for (int tn = 0; tn < 4; tn++) {
                    float2 o;
                    o.x = wgt * c[tm][tn][half_m * 2 + 0];
                    o.y = wgt * c[tm][tn][half_m * 2 + 1];
                    *(float2*)(g_O + orow + tn * 8) = o;
                }
            }
        }
    }
}

// ======================= combine =======================
__global__ void k_combine(float* __restrict__ y) {
    int i = blockIdx.x * blockDim.x + threadIdx.x;
    const int V = DIM / 4;
    if (i >= N_TOK * V) return;
    int tok = i / V;
    int c   = i - tok * V;
    int p0 = g_tok2pair[2 * tok];
    int p1 = g_tok2pair[2 * tok + 1];
    float4 a = ((const float4*)(g_O + (size_t)p0 * DIM))[c];
    float4 b = ((const float4*)(g_O + (size_t)p1 * DIM))[c];
    float4 r;
    r.x = a.x + b.x; r.y = a.y + b.y; r.z = a.z + b.z; r.w = a.w + b.w;
    ((float4*)y)[i] = r;
}

// ======================= launch =======================
extern "C" void kernel_launch(void* const* d_in, const int* in_sizes, int n_in,
                              void* d_out, int out_size) {
    const float* x  = (const float*)d_in[0];   // [N, D]
    const float* gw = (const float*)d_in[1];   // [D, E]
    const float* w1 = (const float*)d_in[2];   // [E, D, DFF]
    const float* w2 = (const float*)d_in[3];   // [E, DFF, D]
    float* y = (float*)d_out;

    cudaFuncSetAttribute((const void*)k_mma<DIM / 32, true>,
                         cudaFuncAttributeMaxDynamicSharedMemorySize, SMEM_BYTES);
    cudaFuncSetAttribute((const void*)k_mma<DFF / 32, false>,
                         cudaFuncAttributeMaxDynamicSharedMemorySize, SMEM_BYTES);

    k_init<<<1, 32>>>();
    k_convert_x<<<(N_TOK * DIM / 4 + 255) / 256, 256>>>(x);

    __nv_bfloat16* w1h; __nv_bfloat16* w2h;
    cudaGetSymbolAddress((void**)&w1h, g_W1t);
    cudaGetSymbolAddress((void**)&w2h, g_W2t);
    __nv_bfloat16* w1l = w1h + (size_t)NEXP * DFF * DIM;
    __nv_bfloat16* w2l = w2h + (size_t)NEXP * DIM * DFF;

    // W1: [e][K=1024][N=4096] -> [e][n][k]
    k_convert_w<<<dim3(DFF / 32, DIM / 32, NEXP), dim3(32, 8)>>>(w1, w1h, w1l, DIM, DFF);
    // W2: [e][K=4096][N=1024] -> [e][d][f]
    k_convert_w<<<dim3(DIM / 32, DFF / 32, NEXP), dim3(32, 8)>>>(w2, w2h, w2l, DFF, DIM);

    k_router<<<N_TOK / 8, 256>>>(x, gw);
    k_prefix<<<1, 32>>>();
    k_assign<<<(N_TOK + 255) / 256, 256>>>();

    k_mma<DIM / 32, true><<<dim3(DFF / 128, NPAIR / 128, NEXP), 256, SMEM_BYTES>>>();
    k_mma<DFF / 32, false><<<dim3(DIM / 128, NPAIR / 128, NEXP), 256, SMEM_BYTES>>>();

    k_combine<<<(N_TOK * DIM / 4 + 255) / 256, 256>>>(y);
}

// round 5
// speedup vs baseline: 5.2857x; 2.1264x over previous
#include <cuda_runtime.h>
#include <cuda_fp16.h>
#include <math.h>
#include <stdint.h>

#define N_TOK 8192
#define DIM   1024
#define NEXP  8
#define DFF   4096
#define NPAIR (2 * N_TOK)

// ======================= device scratch (statics only) =======================
__device__ __half g_X[(size_t)N_TOK * DIM];            // x fp16
__device__ __half g_W1t[(size_t)NEXP * DFF * DIM];     // [e][n][k] fp16
__device__ __half g_W2t[(size_t)NEXP * DIM * DFF];     // [e][d][f] fp16
__device__ __half g_H[(size_t)NPAIR * DFF];            // silu(h) fp16
__device__ float g_O[(size_t)NPAIR * DIM];
__device__ int   g_count[NEXP], g_offset[NEXP], g_cursor[NEXP];
__device__ int   g_pair_token[NPAIR];
__device__ float g_pair_weight[NPAIR];
__device__ int   g_tok2pair[NPAIR];
__device__ int   g_tok_e[NPAIR];
__device__ float g_tok_w[NPAIR];

// ======================= PTX helpers =======================
__device__ __forceinline__ uint32_t smem_u32(const void* p) {
    uint32_t a;
    asm("{ .reg .u64 t; cvta.to.shared.u64 t, %1; cvt.u32.u64 %0, t; }"
        : "=r"(a) : "l"(p));
    return a;
}
__device__ __forceinline__ void cp16(uint32_t dst, const void* src, bool valid) {
    int sz = valid ? 16 : 0;
    asm volatile("cp.async.cg.shared.global [%0], [%1], 16, %2;"
                 :: "r"(dst), "l"(src), "r"(sz));
}
#define CP_COMMIT() asm volatile("cp.async.commit_group;" ::: "memory")
#define CP_WAIT(n)  asm volatile("cp.async.wait_group %0;" :: "n"(n) : "memory")

__device__ __forceinline__ void ldsm_x4(uint32_t* r, uint32_t addr) {
    asm volatile("ldmatrix.sync.aligned.m8n8.x4.shared.b16 {%0,%1,%2,%3}, [%4];"
                 : "=r"(r[0]), "=r"(r[1]), "=r"(r[2]), "=r"(r[3]) : "r"(addr));
}
__device__ __forceinline__ void mma_fp16(float* c, const uint32_t* a,
                                         uint32_t b0, uint32_t b1) {
    asm volatile("mma.sync.aligned.m16n8k16.row.col.f32.f16.f16.f32 "
                 "{%0,%1,%2,%3},{%4,%5,%6,%7},{%8,%9},{%0,%1,%2,%3};"
                 : "+f"(c[0]), "+f"(c[1]), "+f"(c[2]), "+f"(c[3])
                 : "r"(a[0]), "r"(a[1]), "r"(a[2]), "r"(a[3]), "r"(b0), "r"(b1));
}

// ======================= routing kernels =======================
__global__ void k_init() {
    int t = threadIdx.x;
    if (t < NEXP) { g_count[t] = 0; g_cursor[t] = 0; }
}

__global__ void k_router(const float* __restrict__ x, const float* __restrict__ gw) {
    int warp = (blockIdx.x * blockDim.x + threadIdx.x) >> 5;
    int lane = threadIdx.x & 31;
    if (warp >= N_TOK) return;
    const float* xr = x + (size_t)warp * DIM;
    float acc[NEXP];
#pragma unroll
    for (int e = 0; e < NEXP; e++) acc[e] = 0.f;
    for (int d = lane; d < DIM; d += 32) {
        float xv = xr[d];
        const float4* g4 = (const float4*)(gw + (size_t)d * NEXP);
        float4 a = g4[0], b = g4[1];
        acc[0] += xv * a.x; acc[1] += xv * a.y; acc[2] += xv * a.z; acc[3] += xv * a.w;
        acc[4] += xv * b.x; acc[5] += xv * b.y; acc[6] += xv * b.z; acc[7] += xv * b.w;
    }
#pragma unroll
    for (int e = 0; e < NEXP; e++)
#pragma unroll
        for (int s = 16; s > 0; s >>= 1)
            acc[e] += __shfl_xor_sync(0xFFFFFFFFu, acc[e], s);
    if (lane == 0) {
        int e0 = 0; float b0 = acc[0];
#pragma unroll
        for (int e = 1; e < NEXP; e++) if (acc[e] > b0) { b0 = acc[e]; e0 = e; }
        int e1 = -1; float b1 = -INFINITY;
#pragma unroll
        for (int e = 0; e < NEXP; e++) if (e != e0 && acc[e] > b1) { b1 = acc[e]; e1 = e; }
        float w0 = 1.f / (1.f + expf(b1 - b0));
        g_tok_e[2 * warp] = e0;      g_tok_e[2 * warp + 1] = e1;
        g_tok_w[2 * warp] = w0;      g_tok_w[2 * warp + 1] = 1.f - w0;
        atomicAdd(&g_count[e0], 1);
        atomicAdd(&g_count[e1], 1);
    }
}

__global__ void k_prefix() {
    if (threadIdx.x == 0) {
        int s = 0;
        for (int e = 0; e < NEXP; e++) { g_offset[e] = s; s += g_count[e]; }
    }
}

__global__ void k_assign() {
    int t = blockIdx.x * blockDim.x + threadIdx.x;
    if (t >= N_TOK) return;
#pragma unroll
    for (int s = 0; s < 2; s++) {
        int e = g_tok_e[2 * t + s];
        int pos = g_offset[e] + atomicAdd(&g_cursor[e], 1);
        g_pair_token[pos]  = t;
        g_pair_weight[pos] = g_tok_w[2 * t + s];
        g_tok2pair[2 * t + s] = pos;
    }
}

// ======================= converts =======================
__global__ void k_convert_x(const float* __restrict__ x) {
    size_t i = (size_t)blockIdx.x * blockDim.x + threadIdx.x;   // over float4s
    if (i >= (size_t)N_TOK * DIM / 4) return;
    float4 v = ((const float4*)x)[i];
    __half2 a = __floats2half2_rn(v.x, v.y);
    __half2 b = __floats2half2_rn(v.z, v.w);
    ((__half2*)&g_X[i * 4])[0] = a;
    ((__half2*)&g_X[i * 4])[1] = b;
}

// W: [e][K][Ncols] fp32  ->  T: [e][Ncols][K] fp16 (transposed)
__global__ void k_convert_w(const float* __restrict__ W,
                            __half* __restrict__ T,
                            int K, int Ncols) {
    __shared__ float tile[32][33];
    int e = blockIdx.z;
    int n0 = blockIdx.x * 32, k0 = blockIdx.y * 32;
    int tid = threadIdx.x;                 // 256 threads
    const float* We = W + (size_t)e * K * Ncols;
    {
        int tx = tid & 31, ty = tid >> 5;  // (32, 8)
#pragma unroll
        for (int j = 0; j < 4; j++)
            tile[ty + 8 * j][tx] = We[(size_t)(k0 + ty + 8 * j) * Ncols + n0 + tx];
    }
    __syncthreads();
    size_t obase = (size_t)e * Ncols * K;
    {
        int kp = tid & 15;                 // k pair index (k = 2*kp)
        int nb = tid >> 4;                 // 0..15
#pragma unroll
        for (int jn = 0; jn < 2; jn++) {
            int n = nb + 16 * jn;
            __half2 h = __floats2half2_rn(tile[kp * 2][n], tile[kp * 2 + 1][n]);
            *(__half2*)&T[obase + (size_t)(n0 + n) * K + k0 + kp * 2] = h;
        }
    }
}

// ======================= mma.sync GEMM =======================
// Smem stage: 2 planes (A, B), each 128 rows x 32 fp16, row stride 80B.
#define ROW_B   80
#define PLANE_B (128 * ROW_B)           // 10240
#define STAGE_B (2 * PLANE_B)           // 20480
#define NSTAGE  3
#define SMEM_BYTES (NSTAGE * STAGE_B)   // 61440 -> 2 CTAs/SM

// G1: H = silu(X_gathered @ W1t^T)   K=1024 (NC=32)
// !G1: O = w * (H @ W2t^T)           K=4096 (NC=128)
template <int NC, bool G1>
__global__ __launch_bounds__(256, 2) void k_mma() {
    const int e    = blockIdx.z;
    const int cnt  = g_count[e];
    const int row0 = blockIdx.y * 128;
    if (row0 >= cnt) return;
    const int off  = g_offset[e];
    const int n0   = blockIdx.x * 128;

    extern __shared__ char dynsmem[];
    const uint32_t sb = smem_u32(dynsmem);

    const int tid  = threadIdx.x;
    const int lane = tid & 31;
    const int wid  = tid >> 5;
    const int wm   = wid & 1;      // 0..1 (64 rows each)
    const int wn   = wid >> 1;     // 0..3 (32 cols each)

    // ---- global load: thread loads row r = tid>>1, half = tid&1 (32B) ----
    const int r    = tid >> 1;
    const int half = tid & 1;
    const int row  = row0 + r;
    const bool vA  = row < cnt;

    const char* srcA;
    const char* srcB;
    if (G1) {
        int tok = vA ? g_pair_token[off + row] : 0;
        srcA = (const char*)(&g_X[0] + (size_t)tok * DIM) + half * 32;
        srcB = (const char*)(&g_W1t[0] + ((size_t)e * DFF + n0 + r) * DIM) + half * 32;
    } else {
        size_t p = (size_t)(vA ? off + row : 0);
        srcA = (const char*)(&g_H[0] + p * DFF) + half * 32;
        srcB = (const char*)(&g_W2t[0] + ((size_t)e * DIM + n0 + r) * DFF) + half * 32;
    }
    const uint32_t dstOff = (uint32_t)(r * ROW_B + half * 32);

    // ---- ldmatrix per-thread addresses (within a plane) ----
    const int mat  = lane >> 3;
    const int lrow = lane & 7;
    const uint32_t aOff = (uint32_t)((wm * 64 + (mat & 1) * 8 + lrow) * ROW_B + (mat >> 1) * 16);
    const uint32_t bOff = (uint32_t)((wn * 32 + (mat >> 1) * 8 + lrow) * ROW_B + (mat & 1) * 16);

    float c[4][4][4];
#pragma unroll
    for (int i = 0; i < 4; i++)
#pragma unroll
        for (int j = 0; j < 4; j++)
#pragma unroll
            for (int q = 0; q < 4; q++) c[i][j][q] = 0.f;

    auto load_stage = [&](int cidx) {
        uint32_t st = sb + (uint32_t)(cidx % NSTAGE) * STAGE_B;
        size_t ko = (size_t)cidx * 64;   // 32 fp16 = 64 bytes per chunk
        cp16(st + dstOff,               srcA + ko,      vA);
        cp16(st + dstOff + 16,          srcA + ko + 16, vA);
        cp16(st + PLANE_B + dstOff,      srcB + ko,      true);
        cp16(st + PLANE_B + dstOff + 16, srcB + ko + 16, true);
        CP_COMMIT();
    };

    load_stage(0);
    load_stage(1);

    for (int cidx = 0; cidx < NC; cidx++) {
        if (cidx + 2 < NC) { CP_WAIT(1); } else { CP_WAIT(0); }
        __syncthreads();
        if (cidx + 2 < NC) load_stage(cidx + 2);

        uint32_t st = sb + (uint32_t)(cidx % NSTAGE) * STAGE_B;
#pragma unroll
        for (int ks = 0; ks < 2; ks++) {
            uint32_t kso = (uint32_t)(ks * 32);
            uint32_t a[4][4], b[2][4];
#pragma unroll
            for (int tm = 0; tm < 4; tm++)
                ldsm_x4(a[tm], st + aOff + (uint32_t)(tm * 16 * ROW_B) + kso);
#pragma unroll
            for (int tp = 0; tp < 2; tp++)
                ldsm_x4(b[tp], st + PLANE_B + bOff + (uint32_t)(tp * 16 * ROW_B) + kso);
#pragma unroll
            for (int tm = 0; tm < 4; tm++)
#pragma unroll
                for (int tp = 0; tp < 2; tp++) {
                    mma_fp16(c[tm][tp * 2 + 0], a[tm], b[tp][0], b[tp][1]);
                    mma_fp16(c[tm][tp * 2 + 1], a[tm], b[tp][2], b[tp][3]);
                }
        }
    }

    // ---- epilogue ----
    const int g   = lane >> 2;
    const int tig = lane & 3;
#pragma unroll
    for (int tm = 0; tm < 4; tm++) {
#pragma unroll
        for (int half_m = 0; half_m < 2; half_m++) {
            int rr = row0 + wm * 64 + tm * 16 + g + half_m * 8;
            if (rr >= cnt) continue;
            if (G1) {
                size_t hrow = (size_t)(off + rr) * DFF + n0 + wn * 32 + tig * 2;
#pragma unroll
                for (int tn = 0; tn < 4; tn++) {
                    float v0 = c[tm][tn][half_m * 2 + 0];
                    float v1 = c[tm][tn][half_m * 2 + 1];
                    v0 = v0 / (1.f + __expf(-v0));
                    v1 = v1 / (1.f + __expf(-v1));
                    *(__half2*)(&g_H[0] + hrow + tn * 8) = __floats2half2_rn(v0, v1);
                }
            } else {
                float wgt = g_pair_weight[off + rr];
                size_t orow = (size_t)(off + rr) * DIM + n0 + wn * 32 + tig * 2;
#pragma unroll
                for (int tn = 0; tn < 4; tn++) {
                    float2 o;
                    o.x = wgt * c[tm][tn][half_m * 2 + 0];
                    o.y = wgt * c[tm][tn][half_m * 2 + 1];
                    *(float2*)(g_O + orow + tn * 8) = o;
                }
            }
        }
    }
}

// ======================= combine =======================
__global__ void k_combine(float* __restrict__ y) {
    int i = blockIdx.x * blockDim.x + threadIdx.x;
    const int V = DIM / 4;
    if (i >= N_TOK * V) return;
    int tok = i / V;
    int c   = i - tok * V;
    int p0 = g_tok2pair[2 * tok];
    int p1 = g_tok2pair[2 * tok + 1];
    float4 a = ((const float4*)(g_O + (size_t)p0 * DIM))[c];
    float4 b = ((const float4*)(g_O + (size_t)p1 * DIM))[c];
    float4 r;
    r.x = a.x + b.x; r.y = a.y + b.y; r.z = a.z + b.z; r.w = a.w + b.w;
    ((float4*)y)[i] = r;
}

// ======================= launch =======================
extern "C" void kernel_launch(void* const* d_in, const int* in_sizes, int n_in,
                              void* d_out, int out_size) {
    const float* x  = (const float*)d_in[0];   // [N, D]
    const float* gw = (const float*)d_in[1];   // [D, E]
    const float* w1 = (const float*)d_in[2];   // [E, D, DFF]
    const float* w2 = (const float*)d_in[3];   // [E, DFF, D]
    float* y = (float*)d_out;

    cudaFuncSetAttribute((const void*)k_mma<DIM / 32, true>,
                         cudaFuncAttributeMaxDynamicSharedMemorySize, SMEM_BYTES);
    cudaFuncSetAttribute((const void*)k_mma<DFF / 32, false>,
                         cudaFuncAttributeMaxDynamicSharedMemorySize, SMEM_BYTES);

    k_init<<<1, 32>>>();
    k_convert_x<<<(N_TOK * DIM / 4 + 255) / 256, 256>>>(x);

    __half* w1t; __half* w2t;
    cudaGetSymbolAddress((void**)&w1t, g_W1t);
    cudaGetSymbolAddress((void**)&w2t, g_W2t);

    // W1: [e][K=1024][N=4096] -> [e][n][k]
    k_convert_w<<<dim3(DFF / 32, DIM / 32, NEXP), 256>>>(w1, w1t, DIM, DFF);
    // W2: [e][K=4096][N=1024] -> [e][d][f]
    k_convert_w<<<dim3(DIM / 32, DFF / 32, NEXP), 256>>>(w2, w2t, DFF, DIM);

    k_router<<<N_TOK / 8, 256>>>(x, gw);
    k_prefix<<<1, 32>>>();
    k_assign<<<(N_TOK + 255) / 256, 256>>>();

    k_mma<DIM / 32, true><<<dim3(DFF / 128, NPAIR / 128, NEXP), 256, SMEM_BYTES>>>();
    k_mma<DFF / 32, false><<<dim3(DIM / 128, NPAIR / 128, NEXP), 256, SMEM_BYTES>>>();

    k_combine<<<(N_TOK * DIM / 4 + 255) / 256, 256>>>(y);
}

// round 6
// speedup vs baseline: 5.8645x; 1.1095x over previous
#include <cuda_runtime.h>
#include <cuda_fp16.h>
#include <math.h>
#include <stdint.h>

#define N_TOK 8192
#define DIM   1024
#define NEXP  8
#define DFF   4096
#define NPAIR (2 * N_TOK)

// ======================= device scratch (statics only) =======================
__device__ __half g_X[(size_t)N_TOK * DIM];            // x fp16
__device__ __half g_W1t[(size_t)NEXP * DFF * DIM];     // [e][n][k] fp16
__device__ __half g_W2t[(size_t)NEXP * DIM * DFF];     // [e][d][f] fp16
__device__ __half g_H[(size_t)NPAIR * DFF];            // silu(h) fp16
__device__ float g_O[(size_t)NPAIR * DIM];
__device__ int   g_count[NEXP], g_offset[NEXP], g_cursor[NEXP];
__device__ int   g_pair_token[NPAIR];
__device__ float g_pair_weight[NPAIR];
__device__ int   g_tok2pair[NPAIR];
__device__ int   g_tok_e[NPAIR];
__device__ float g_tok_w[NPAIR];

// ======================= PTX helpers =======================
__device__ __forceinline__ uint32_t smem_u32(const void* p) {
    uint32_t a;
    asm("{ .reg .u64 t; cvta.to.shared.u64 t, %1; cvt.u32.u64 %0, t; }"
        : "=r"(a) : "l"(p));
    return a;
}
__device__ __forceinline__ void cp16(uint32_t dst, const void* src, bool valid) {
    int sz = valid ? 16 : 0;
    asm volatile("cp.async.cg.shared.global [%0], [%1], 16, %2;"
                 :: "r"(dst), "l"(src), "r"(sz));
}
#define CP_COMMIT() asm volatile("cp.async.commit_group;" ::: "memory")
#define CP_WAIT(n)  asm volatile("cp.async.wait_group %0;" :: "n"(n) : "memory")

__device__ __forceinline__ void ldsm_x4(uint32_t* r, uint32_t addr) {
    asm volatile("ldmatrix.sync.aligned.m8n8.x4.shared.b16 {%0,%1,%2,%3}, [%4];"
                 : "=r"(r[0]), "=r"(r[1]), "=r"(r[2]), "=r"(r[3]) : "r"(addr));
}
__device__ __forceinline__ void mma_fp16(float* c, const uint32_t* a,
                                         uint32_t b0, uint32_t b1) {
    asm volatile("mma.sync.aligned.m16n8k16.row.col.f32.f16.f16.f32 "
                 "{%0,%1,%2,%3},{%4,%5,%6,%7},{%8,%9},{%0,%1,%2,%3};"
                 : "+f"(c[0]), "+f"(c[1]), "+f"(c[2]), "+f"(c[3])
                 : "r"(a[0]), "r"(a[1]), "r"(a[2]), "r"(a[3]), "r"(b0), "r"(b1));
}

// ======================= routing kernels =======================
__global__ void k_init() {
    int t = threadIdx.x;
    if (t < NEXP) { g_count[t] = 0; g_cursor[t] = 0; }
}

__global__ void k_router(const float* __restrict__ x, const float* __restrict__ gw) {
    int warp = (blockIdx.x * blockDim.x + threadIdx.x) >> 5;
    int lane = threadIdx.x & 31;
    if (warp >= N_TOK) return;
    const float* xr = x + (size_t)warp * DIM;
    float acc[NEXP];
#pragma unroll
    for (int e = 0; e < NEXP; e++) acc[e] = 0.f;
    for (int d = lane; d < DIM; d += 32) {
        float xv = xr[d];
        const float4* g4 = (const float4*)(gw + (size_t)d * NEXP);
        float4 a = g4[0], b = g4[1];
        acc[0] += xv * a.x; acc[1] += xv * a.y; acc[2] += xv * a.z; acc[3] += xv * a.w;
        acc[4] += xv * b.x; acc[5] += xv * b.y; acc[6] += xv * b.z; acc[7] += xv * b.w;
    }
#pragma unroll
    for (int e = 0; e < NEXP; e++)
#pragma unroll
        for (int s = 16; s > 0; s >>= 1)
            acc[e] += __shfl_xor_sync(0xFFFFFFFFu, acc[e], s);
    if (lane == 0) {
        int e0 = 0; float b0 = acc[0];
#pragma unroll
        for (int e = 1; e < NEXP; e++) if (acc[e] > b0) { b0 = acc[e]; e0 = e; }
        int e1 = -1; float b1 = -INFINITY;
#pragma unroll
        for (int e = 0; e < NEXP; e++) if (e != e0 && acc[e] > b1) { b1 = acc[e]; e1 = e; }
        float w0 = 1.f / (1.f + expf(b1 - b0));
        g_tok_e[2 * warp] = e0;      g_tok_e[2 * warp + 1] = e1;
        g_tok_w[2 * warp] = w0;      g_tok_w[2 * warp + 1] = 1.f - w0;
        atomicAdd(&g_count[e0], 1);
        atomicAdd(&g_count[e1], 1);
    }
}

__global__ void k_prefix() {
    if (threadIdx.x == 0) {
        int s = 0;
        for (int e = 0; e < NEXP; e++) { g_offset[e] = s; s += g_count[e]; }
    }
}

__global__ void k_assign() {
    int t = blockIdx.x * blockDim.x + threadIdx.x;
    if (t >= N_TOK) return;
#pragma unroll
    for (int s = 0; s < 2; s++) {
        int e = g_tok_e[2 * t + s];
        int pos = g_offset[e] + atomicAdd(&g_cursor[e], 1);
        g_pair_token[pos]  = t;
        g_pair_weight[pos] = g_tok_w[2 * t + s];
        g_tok2pair[2 * t + s] = pos;
    }
}

// ======================= converts =======================
__global__ void k_convert_x(const float* __restrict__ x) {
    size_t i = (size_t)blockIdx.x * blockDim.x + threadIdx.x;   // over float4s
    if (i >= (size_t)N_TOK * DIM / 4) return;
    float4 v = ((const float4*)x)[i];
    __half2 a = __floats2half2_rn(v.x, v.y);
    __half2 b = __floats2half2_rn(v.z, v.w);
    ((__half2*)&g_X[i * 4])[0] = a;
    ((__half2*)&g_X[i * 4])[1] = b;
}

// W: [e][K][Ncols] fp32  ->  T: [e][Ncols][K] fp16 (transposed)
__global__ void k_convert_w(const float* __restrict__ W,
                            __half* __restrict__ T,
                            int K, int Ncols) {
    __shared__ float tile[32][33];
    int e = blockIdx.z;
    int n0 = blockIdx.x * 32, k0 = blockIdx.y * 32;
    int tid = threadIdx.x;                 // 256 threads
    const float* We = W + (size_t)e * K * Ncols;
    {
        int tx = tid & 31, ty = tid >> 5;  // (32, 8)
#pragma unroll
        for (int j = 0; j < 4; j++)
            tile[ty + 8 * j][tx] = We[(size_t)(k0 + ty + 8 * j) * Ncols + n0 + tx];
    }
    __syncthreads();
    size_t obase = (size_t)e * Ncols * K;
    {
        int kp = tid & 15;                 // k pair index (k = 2*kp)
        int nb = tid >> 4;                 // 0..15
#pragma unroll
        for (int jn = 0; jn < 2; jn++) {
            int n = nb + 16 * jn;
            __half2 h = __floats2half2_rn(tile[kp * 2][n], tile[kp * 2 + 1][n]);
            *(__half2*)&T[obase + (size_t)(n0 + n) * K + k0 + kp * 2] = h;
        }
    }
}

// ======================= mma.sync GEMM =======================
// Stage: 2 planes (A, B), each 128 rows x 64 fp16 = 128B/row, SW128 XOR swizzle.
#define PLANE_B (128 * 128)             // 16384
#define STAGE_B (2 * PLANE_B)           // 32768
#define SMEM_BYTES (2 * STAGE_B)        // 65536 -> 2 CTAs/SM

static __device__ __forceinline__ uint32_t swz(uint32_t off) {
    return off ^ ((off >> 3) & 0x70);
}

// G1: H = silu(X_gathered @ W1t^T)   K=1024 (NC=16)
// !G1: O = w * (H @ W2t^T)           K=4096 (NC=64)
template <int NC, bool G1>
__global__ __launch_bounds__(256, 2) void k_mma() {
    const int e    = blockIdx.z;
    const int cnt  = g_count[e];
    const int row0 = blockIdx.y * 128;
    if (row0 >= cnt) return;
    const int off  = g_offset[e];
    const int n0   = blockIdx.x * 128;

    extern __shared__ char dynsmem[];
    const uint32_t sb = smem_u32(dynsmem);

    const int tid  = threadIdx.x;
    const int lane = tid & 31;
    const int wid  = tid >> 5;
    const int wm   = wid & 1;      // 0..1 (64 rows each)
    const int wn   = wid >> 1;     // 0..3 (32 cols each)

    // ---- global load: thread loads row r = tid>>1, half = tid&1 (64B) ----
    const int r    = tid >> 1;
    const int half = tid & 1;
    const int row  = row0 + r;
    const bool vA  = row < cnt;

    const char* srcA;   // points at this thread's 64B segment in chunk 0
    const char* srcB;
    if (G1) {
        int tok = vA ? g_pair_token[off + row] : 0;
        srcA = (const char*)(&g_X[0] + (size_t)tok * DIM) + half * 64;
        srcB = (const char*)(&g_W1t[0] + ((size_t)e * DFF + n0 + r) * DIM) + half * 64;
    } else {
        size_t p = (size_t)(vA ? off + row : 0);
        srcA = (const char*)(&g_H[0] + p * DFF) + half * 64;
        srcB = (const char*)(&g_W2t[0] + ((size_t)e * DIM + n0 + r) * DFF) + half * 64;
    }
    uint32_t dstO[4];
#pragma unroll
    for (int j = 0; j < 4; j++)
        dstO[j] = swz((uint32_t)(r * 128 + half * 64 + j * 16));

    // ---- ldmatrix addressing: XOR mask reduces to lrow<<4 (const per thread) ----
    const int mat  = lane >> 3;
    const int lrow = lane & 7;
    const uint32_t xmask = (uint32_t)(lrow << 4);
    // A: row = wm*64 + tm*16 + (mat&1)*8 + lrow ; col bytes = (mat>>1)*16 + ks*32
    const uint32_t aBase = (uint32_t)((wm * 64 + (mat & 1) * 8 + lrow) * 128 + (mat >> 1) * 16);
    // B: row = wn*32 + tp*16 + (mat>>1)*8 + lrow ; col bytes = (mat&1)*16 + ks*32
    const uint32_t bBase = (uint32_t)((wn * 32 + (mat >> 1) * 8 + lrow) * 128 + (mat & 1) * 16);

    float c[4][4][4];
#pragma unroll
    for (int i = 0; i < 4; i++)
#pragma unroll
        for (int j = 0; j < 4; j++)
#pragma unroll
            for (int q = 0; q < 4; q++) c[i][j][q] = 0.f;

    auto load_stage = [&](int cidx) {
        uint32_t st = sb + (uint32_t)(cidx & 1) * STAGE_B;
        size_t ko = (size_t)cidx * 128;   // 64 fp16 = 128 bytes per chunk
#pragma unroll
        for (int j = 0; j < 4; j++)
            cp16(st + dstO[j], srcA + ko + j * 16, vA);
#pragma unroll
        for (int j = 0; j < 4; j++)
            cp16(st + PLANE_B + dstO[j], srcB + ko + j * 16, true);
        CP_COMMIT();
    };

    load_stage(0);

    for (int cidx = 0; cidx < NC; cidx++) {
        CP_WAIT(0);                 // stage cidx landed (this thread's view)
        __syncthreads();            // all threads' data visible; prev compute done
        if (cidx + 1 < NC) load_stage(cidx + 1);

        uint32_t st = sb + (uint32_t)(cidx & 1) * STAGE_B;
#pragma unroll
        for (int ks = 0; ks < 4; ks++) {
            uint32_t kso = (uint32_t)(ks * 32);
            uint32_t a[4][4], b[2][4];
#pragma unroll
            for (int tm = 0; tm < 4; tm++)
                ldsm_x4(a[tm], st + ((aBase + (uint32_t)(tm * 16 * 128) + kso) ^ xmask));
#pragma unroll
            for (int tp = 0; tp < 2; tp++)
                ldsm_x4(b[tp], st + PLANE_B + ((bBase + (uint32_t)(tp * 16 * 128) + kso) ^ xmask));
#pragma unroll
            for (int tm = 0; tm < 4; tm++)
#pragma unroll
                for (int tp = 0; tp < 2; tp++) {
                    mma_fp16(c[tm][tp * 2 + 0], a[tm], b[tp][0], b[tp][1]);
                    mma_fp16(c[tm][tp * 2 + 1], a[tm], b[tp][2], b[tp][3]);
                }
        }
    }

    // ---- epilogue ----
    const int g   = lane >> 2;
    const int tig = lane & 3;
#pragma unroll
    for (int tm = 0; tm < 4; tm++) {
#pragma unroll
        for (int half_m = 0; half_m < 2; half_m++) {
            int rr = row0 + wm * 64 + tm * 16 + g + half_m * 8;
            if (rr >= cnt) continue;
            if (G1) {
                size_t hrow = (size_t)(off + rr) * DFF + n0 + wn * 32 + tig * 2;
#pragma unroll
                for (int tn = 0; tn < 4; tn++) {
                    float v0 = c[tm][tn][half_m * 2 + 0];
                    float v1 = c[tm][tn][half_m * 2 + 1];
                    v0 = v0 / (1.f + __expf(-v0));
                    v1 = v1 / (1.f + __expf(-v1));
                    *(__half2*)(&g_H[0] + hrow + tn * 8) = __floats2half2_rn(v0, v1);
                }
            } else {
                float wgt = g_pair_weight[off + rr];
                size_t orow = (size_t)(off + rr) * DIM + n0 + wn * 32 + tig * 2;
#pragma unroll
                for (int tn = 0; tn < 4; tn++) {
                    float2 o;
                    o.x = wgt * c[tm][tn][half_m * 2 + 0];
                    o.y = wgt * c[tm][tn][half_m * 2 + 1];
                    *(float2*)(g_O + orow + tn * 8) = o;
                }
            }
        }
    }
}

// ======================= combine =======================
__global__ void k_combine(float* __restrict__ y) {
    int i = blockIdx.x * blockDim.x + threadIdx.x;
    const int V = DIM / 4;
    if (i >= N_TOK * V) return;
    int tok = i / V;
    int c   = i - tok * V;
    int p0 = g_tok2pair[2 * tok];
    int p1 = g_tok2pair[2 * tok + 1];
    float4 a = ((const float4*)(g_O + (size_t)p0 * DIM))[c];
    float4 b = ((const float4*)(g_O + (size_t)p1 * DIM))[c];
    float4 r;
    r.x = a.x + b.x; r.y = a.y + b.y; r.z = a.z + b.z; r.w = a.w + b.w;
    ((float4*)y)[i] = r;
}

// ======================= launch =======================
extern "C" void kernel_launch(void* const* d_in, const int* in_sizes, int n_in,
                              void* d_out, int out_size) {
    const float* x  = (const float*)d_in[0];   // [N, D]
    const float* gw = (const float*)d_in[1];   // [D, E]
    const float* w1 = (const float*)d_in[2];   // [E, D, DFF]
    const float* w2 = (const float*)d_in[3];   // [E, DFF, D]
    float* y = (float*)d_out;

    cudaFuncSetAttribute((const void*)k_mma<DIM / 64, true>,
                         cudaFuncAttributeMaxDynamicSharedMemorySize, SMEM_BYTES);
    cudaFuncSetAttribute((const void*)k_mma<DFF / 64, false>,
                         cudaFuncAttributeMaxDynamicSharedMemorySize, SMEM_BYTES);

    k_init<<<1, 32>>>();
    k_convert_x<<<(N_TOK * DIM / 4 + 255) / 256, 256>>>(x);

    __half* w1t; __half* w2t;
    cudaGetSymbolAddress((void**)&w1t, g_W1t);
    cudaGetSymbolAddress((void**)&w2t, g_W2t);

    // W1: [e][K=1024][N=4096] -> [e][n][k]
    k_convert_w<<<dim3(DFF / 32, DIM / 32, NEXP), 256>>>(w1, w1t, DIM, DFF);
    // W2: [e][K=4096][N=1024] -> [e][d][f]
    k_convert_w<<<dim3(DIM / 32, DFF / 32, NEXP), 256>>>(w2, w2t, DFF, DIM);

    k_router<<<N_TOK / 8, 256>>>(x, gw);
    k_prefix<<<1, 32>>>();
    k_assign<<<(N_TOK + 255) / 256, 256>>>();

    k_mma<DIM / 64, true><<<dim3(DFF / 128, NPAIR / 128, NEXP), 256, SMEM_BYTES>>>();
    k_mma<DFF / 64, false><<<dim3(DIM / 128, NPAIR / 128, NEXP), 256, SMEM_BYTES>>>();

    k_combine<<<(N_TOK * DIM / 4 + 255) / 256, 256>>>(y);
}